// round 5
// baseline (speedup 1.0000x reference)
#include <cuda_runtime.h>

#define HH 128
#define WW 128
#define HWN 16384
#define BHW (4 * 16384)
#define BN 4
#define CN 64

typedef unsigned long long ull;

__device__ __constant__ int c_RATES[4] = {2, 3, 5, 9};

// Scratch (static device globals: allocation-free, graph-capturable)
__device__ float g_xhwc[BN * HWN * CN];            // [b][p][c]
__device__ float g_off[4 * 18 * BHW];              // [j][k2][b*HW+p]  planar
__device__ float g_dwt[4 * 9 * 64 * 64];           // [i][k][c][o]
__device__ float g_cat[4 * BN * CN * HWN];         // [i][b][o][p]
__device__ float g_bsums[4 * BN * 128 * 64];       // [i][b][row][o]
__device__ float g_gate[BN * 256];                 // 1 + sigmoid(...)

__device__ __forceinline__ ull pack2(float a, float b) {
    ull r;
    asm("mov.b64 %0, {%1, %2};" : "=l"(r) : "f"(a), "f"(b));
    return r;
}
__device__ __forceinline__ void ffma2(ull& d, ull a, ull b) {
    asm("fma.rn.f32x2 %0, %1, %2, %0;" : "+l"(d) : "l"(a), "l"(b));
}

// ---------------- K1: NCHW -> NHWC transpose of x ----------------
__global__ void transpose_kernel(const float* __restrict__ x) {
    __shared__ float tile[32][33];
    int b  = blockIdx.z;
    int p0 = blockIdx.x * 32;
    int c0 = blockIdx.y * 32;
    for (int i = threadIdx.y; i < 32; i += 8)
        tile[i][threadIdx.x] = x[(b * 64 + c0 + i) * HWN + p0 + threadIdx.x];
    __syncthreads();
    for (int i = threadIdx.y; i < 32; i += 8)
        g_xhwc[(b * HWN + p0 + i) * 64 + c0 + threadIdx.x] = tile[threadIdx.x][i];
}

// ---------------- K1b: dw (i,o,c,3,3) -> g_dwt [i][k][c][o] ----------------
__global__ void dwt_kernel(const float* __restrict__ dw) {
    int idx = blockIdx.x * 256 + threadIdx.x;  // < 147456
    int i  = idx / 36864;
    int r  = idx % 36864;
    int k  = r / 4096;
    int r2 = r & 4095;
    int c  = r2 >> 6;
    int o  = r2 & 63;
    g_dwt[idx] = dw[((i * 64 + o) * 64 + c) * 9 + k];
}

// ---------------- K2: offset conv (64 -> 18, dilated 3x3, relu), f32x2 ----------------
// writes PLANAR layout: g_off[(j*18+k2)*BHW + b*HWN + p]
__global__ __launch_bounds__(256) void offset_kernel(const float* __restrict__ x,
                                                     const float* __restrict__ ow,
                                                     const float* __restrict__ ob) {
    __shared__ float ow_sh[9 * 64 * 20];
    int j = blockIdx.z, b = blockIdx.y;
    int rate = c_RATES[j];
    int tid = threadIdx.x;
    for (int idx = tid; idx < 9 * 64 * 20; idx += 256) {
        int k2 = idx % 20;
        int rest = idx / 20;
        int c = rest % 64;
        int t = rest / 64;
        ow_sh[idx] = (k2 < 18) ? ow[((j * 18 + k2) * 64 + c) * 9 + t] : 0.f;
    }
    __syncthreads();

    int p = blockIdx.x * 256 + tid;
    int y = p >> 7, xx = p & 127;
    ull acc2[10];
#pragma unroll
    for (int q = 0; q < 9; q++) acc2[q] = pack2(ob[j * 18 + 2 * q], ob[j * 18 + 2 * q + 1]);
    acc2[9] = 0ull;

    const float* xb = x + b * 64 * HWN;
    for (int t = 0; t < 9; t++) {
        int tyv = y + (t / 3 - 1) * rate;
        int txv = xx + (t % 3 - 1) * rate;
        if ((unsigned)tyv >= HH || (unsigned)txv >= WW) continue;
        const float* xp = xb + tyv * WW + txv;
#pragma unroll 4
        for (int c = 0; c < 64; c++) {
            float xc = xp[c * HWN];  // coalesced across warp
            ull xcc = pack2(xc, xc);
            const ull* wr = (const ull*)&ow_sh[(t * 64 + c) * 20];  // broadcast
#pragma unroll
            for (int q = 0; q < 10; q++) ffma2(acc2[q], wr[q], xcc);
        }
    }
    float* og = g_off + j * 18 * BHW + b * HWN + p;  // plane stride BHW, coalesced
#pragma unroll
    for (int q = 0; q < 9; q++) {
        float2 v = *(float2*)&acc2[q];
        og[(2 * q) * BHW]     = fmaxf(v.x, 0.f);
        og[(2 * q + 1) * BHW] = fmaxf(v.y, 0.f);
    }
}

// ---------------- K3: deform sample + GEMM per branch (software-pipelined) ----------------
// block = full image row (128 px) x 64 outputs, 128 threads, 8x8 tile, f32x2
// double-buffered A and S: gather(k+1) overlapped under GEMM(k)
#define SPITCH 132
__global__ __launch_bounds__(128) void branch_kernel() {
    extern __shared__ float smem[];
    // layout: A0[4096] A1[4096] S0[8448] S1[8448]  (total 25088 floats = 100352 B)

    int i = blockIdx.z, b = blockIdx.y, row = blockIdx.x;
    int p0 = row * 128;
    int j = (i + 3) & 3;
    int rate = c_RATES[i];
    int tid = threadIdx.x;
    int tx = tid & 15, ty = tid >> 4;
    int t3 = tid & 3;
    int lsp = tid >> 2;  // 0..31, pixel-within-pass for this thread

    ull acc[8][4];
#pragma unroll
    for (int oy = 0; oy < 8; oy++)
#pragma unroll
        for (int q = 0; q < 4; q++) acc[oy][q] = 0ull;

    const float* xb   = &g_xhwc[b * HWN * 64];
    const float* dwt  = &g_dwt[i * 9 * 4096];
    const float* offb = g_off + j * 18 * BHW + b * HWN + p0;

    // ---- prologue: stage A(0) and gather k=0 into buffers 0 ----
    {
        const float4* src = (const float4*)dwt;
        float4* dst = (float4*)smem;  // A0
#pragma unroll
        for (int u = 0; u < 8; u++) dst[tid + u * 128] = src[tid + u * 128];

        int kyr = -rate, kxr = -rate;  // k=0
        const float* offY = offb;            // k2=0
        const float* offX = offb + BHW;      // k2=1
        float* S0 = smem + 8192;
#pragma unroll
        for (int pass = 0; pass < 4; pass++) {
            int sp = pass * 32 + lsp;
            float dy = __ldg(offY + sp);
            float dx = __ldg(offX + sp);
            float py = (float)(row + kyr) + dy;
            float px = (float)(sp + kxr) + dx;
            float fy = floorf(py), fx = floorf(px);
            int iy0 = (int)fy, ix0 = (int)fx;
            float wy1 = py - fy, wx1 = px - fx;
            float wy0 = 1.f - wy1, wx0 = 1.f - wx1;
            bool vy0 = (unsigned)iy0 < HH, vy1 = (unsigned)(iy0 + 1) < HH;
            bool vx0 = (unsigned)ix0 < WW, vx1 = (unsigned)(ix0 + 1) < WW;
            float w00 = (vy0 && vx0) ? wy0 * wx0 : 0.f;
            float w01 = (vy0 && vx1) ? wy0 * wx1 : 0.f;
            float w10 = (vy1 && vx0) ? wy1 * wx0 : 0.f;
            float w11 = (vy1 && vx1) ? wy1 * wx1 : 0.f;
            ull w00d = pack2(w00, w00), w01d = pack2(w01, w01);
            ull w10d = pack2(w10, w10), w11d = pack2(w11, w11);
            int cy0 = min(max(iy0, 0), HH - 1), cy1 = min(max(iy0 + 1, 0), HH - 1);
            int cx0 = min(max(ix0, 0), WW - 1), cx1 = min(max(ix0 + 1, 0), WW - 1);
            const float* b00 = xb + (cy0 * WW + cx0) * 64;
            const float* b01 = xb + (cy0 * WW + cx1) * 64;
            const float* b10 = xb + (cy1 * WW + cx0) * 64;
            const float* b11 = xb + (cy1 * WW + cx1) * 64;
#pragma unroll
            for (int u = 0; u < 4; u++) {
                int c0 = t3 * 4 + u * 16;
                ulonglong2 t00 = *(const ulonglong2*)(b00 + c0);
                ulonglong2 t01 = *(const ulonglong2*)(b01 + c0);
                ulonglong2 t10 = *(const ulonglong2*)(b10 + c0);
                ulonglong2 t11 = *(const ulonglong2*)(b11 + c0);
                ull r0 = 0, r1 = 0;
                ffma2(r0, w00d, t00.x); ffma2(r1, w00d, t00.y);
                ffma2(r0, w01d, t01.x); ffma2(r1, w01d, t01.y);
                ffma2(r0, w10d, t10.x); ffma2(r1, w10d, t10.y);
                ffma2(r0, w11d, t11.x); ffma2(r1, w11d, t11.y);
                float2 f0 = *(float2*)&r0, f1 = *(float2*)&r1;
                float* d = &S0[c0 * SPITCH + sp];
                d[0]          = f0.x;
                d[SPITCH]     = f0.y;
                d[2 * SPITCH] = f1.x;
                d[3 * SPITCH] = f1.y;
            }
        }
    }
    __syncthreads();

    // ---- main pipelined loop ----
    for (int k = 0; k < 9; k++) {
        int cur = k & 1;
        const float* Ac = smem + cur * 4096;
        const float* Sc = smem + 8192 + cur * 8448;
        float* An = smem + (cur ^ 1) * 4096;
        float* Sn = smem + 8192 + (cur ^ 1) * 8448;
        bool pf = (k < 8);
        int kn = k + 1;
        int kyr = 0, kxr = 0;
        const float* offY = offb;
        const float* offX = offb;
        float dyv[4], dxv[4];
        if (pf) {
            kyr = (kn / 3 - 1) * rate;
            kxr = (kn % 3 - 1) * rate;
            offY = offb + (2 * kn) * BHW;
            offX = offb + (2 * kn + 1) * BHW;
#pragma unroll
            for (int p = 0; p < 4; p++) {
                dyv[p] = __ldg(offY + p * 32 + lsp);
                dxv[p] = __ldg(offX + p * 32 + lsp);
            }
        }

#pragma unroll
        for (int pass = 0; pass < 4; pass++) {
            ulonglong2 t00[4], t01[4], t10[4], t11[4];
            ull w00d = 0, w01d = 0, w10d = 0, w11d = 0;
            int sp = pass * 32 + lsp;
            if (pf) {
                // stage A(k+1) slice (2 float4)
                const float4* asrc = (const float4*)(dwt + kn * 4096);
                ((float4*)An)[pass * 256 + tid]       = asrc[pass * 256 + tid];
                ((float4*)An)[pass * 256 + 128 + tid] = asrc[pass * 256 + 128 + tid];
                // compute tap weights + issue tap loads (latency hidden by GEMM chunk below)
                float dy = dyv[pass], dx = dxv[pass];
                float py = (float)(row + kyr) + dy;
                float px = (float)(sp + kxr) + dx;
                float fy = floorf(py), fx = floorf(px);
                int iy0 = (int)fy, ix0 = (int)fx;
                float wy1 = py - fy, wx1 = px - fx;
                float wy0 = 1.f - wy1, wx0 = 1.f - wx1;
                bool vy0 = (unsigned)iy0 < HH, vy1 = (unsigned)(iy0 + 1) < HH;
                bool vx0 = (unsigned)ix0 < WW, vx1 = (unsigned)(ix0 + 1) < WW;
                float w00 = (vy0 && vx0) ? wy0 * wx0 : 0.f;
                float w01 = (vy0 && vx1) ? wy0 * wx1 : 0.f;
                float w10 = (vy1 && vx0) ? wy1 * wx0 : 0.f;
                float w11 = (vy1 && vx1) ? wy1 * wx1 : 0.f;
                w00d = pack2(w00, w00); w01d = pack2(w01, w01);
                w10d = pack2(w10, w10); w11d = pack2(w11, w11);
                int cy0 = min(max(iy0, 0), HH - 1), cy1 = min(max(iy0 + 1, 0), HH - 1);
                int cx0 = min(max(ix0, 0), WW - 1), cx1 = min(max(ix0 + 1, 0), WW - 1);
                const float* b00 = xb + (cy0 * WW + cx0) * 64;
                const float* b01 = xb + (cy0 * WW + cx1) * 64;
                const float* b10 = xb + (cy1 * WW + cx0) * 64;
                const float* b11 = xb + (cy1 * WW + cx1) * 64;
#pragma unroll
                for (int u = 0; u < 4; u++) {
                    int c0 = t3 * 4 + u * 16;
                    t00[u] = *(const ulonglong2*)(b00 + c0);
                    t01[u] = *(const ulonglong2*)(b01 + c0);
                    t10[u] = *(const ulonglong2*)(b10 + c0);
                    t11[u] = *(const ulonglong2*)(b11 + c0);
                }
            }
            // GEMM chunk: 16 c from current buffers (covers tap-load latency)
#pragma unroll
            for (int cc = 0; cc < 16; cc++) {
                int c = pass * 16 + cc;
                float4 a0 = *(const float4*)&Ac[c * 64 + ty * 8];
                float4 a1 = *(const float4*)&Ac[c * 64 + ty * 8 + 4];
                ulonglong2 B0 = *(const ulonglong2*)&Sc[c * SPITCH + tx * 4];
                ulonglong2 B1 = *(const ulonglong2*)&Sc[c * SPITCH + 64 + tx * 4];
                ull aa;
                aa = pack2(a0.x, a0.x); ffma2(acc[0][0], aa, B0.x); ffma2(acc[0][1], aa, B0.y); ffma2(acc[0][2], aa, B1.x); ffma2(acc[0][3], aa, B1.y);
                aa = pack2(a0.y, a0.y); ffma2(acc[1][0], aa, B0.x); ffma2(acc[1][1], aa, B0.y); ffma2(acc[1][2], aa, B1.x); ffma2(acc[1][3], aa, B1.y);
                aa = pack2(a0.z, a0.z); ffma2(acc[2][0], aa, B0.x); ffma2(acc[2][1], aa, B0.y); ffma2(acc[2][2], aa, B1.x); ffma2(acc[2][3], aa, B1.y);
                aa = pack2(a0.w, a0.w); ffma2(acc[3][0], aa, B0.x); ffma2(acc[3][1], aa, B0.y); ffma2(acc[3][2], aa, B1.x); ffma2(acc[3][3], aa, B1.y);
                aa = pack2(a1.x, a1.x); ffma2(acc[4][0], aa, B0.x); ffma2(acc[4][1], aa, B0.y); ffma2(acc[4][2], aa, B1.x); ffma2(acc[4][3], aa, B1.y);
                aa = pack2(a1.y, a1.y); ffma2(acc[5][0], aa, B0.x); ffma2(acc[5][1], aa, B0.y); ffma2(acc[5][2], aa, B1.x); ffma2(acc[5][3], aa, B1.y);
                aa = pack2(a1.z, a1.z); ffma2(acc[6][0], aa, B0.x); ffma2(acc[6][1], aa, B0.y); ffma2(acc[6][2], aa, B1.x); ffma2(acc[6][3], aa, B1.y);
                aa = pack2(a1.w, a1.w); ffma2(acc[7][0], aa, B0.x); ffma2(acc[7][1], aa, B0.y); ffma2(acc[7][2], aa, B1.x); ffma2(acc[7][3], aa, B1.y);
            }
            // lerp + store into next S buffer
            if (pf) {
#pragma unroll
                for (int u = 0; u < 4; u++) {
                    int c0 = t3 * 4 + u * 16;
                    ull r0 = 0, r1 = 0;
                    ffma2(r0, w00d, t00[u].x); ffma2(r1, w00d, t00[u].y);
                    ffma2(r0, w01d, t01[u].x); ffma2(r1, w01d, t01[u].y);
                    ffma2(r0, w10d, t10[u].x); ffma2(r1, w10d, t10[u].y);
                    ffma2(r0, w11d, t11[u].x); ffma2(r1, w11d, t11[u].y);
                    float2 f0 = *(float2*)&r0, f1 = *(float2*)&r1;
                    float* d = &Sn[c0 * SPITCH + sp];
                    d[0]          = f0.x;
                    d[SPITCH]     = f0.y;
                    d[2 * SPITCH] = f1.x;
                    d[3 * SPITCH] = f1.y;
                }
            }
        }
        __syncthreads();
    }

    // write outputs + per-row channel sums (deterministic)
    float* outp = &g_cat[((i * 4 + b) * 64) * HWN];
    float psum[8];
#pragma unroll
    for (int oy = 0; oy < 8; oy++) {
        int o = ty * 8 + oy;
        float2 p0v = *(float2*)&acc[oy][0];
        float2 p1v = *(float2*)&acc[oy][1];
        float2 p2v = *(float2*)&acc[oy][2];
        float2 p3v = *(float2*)&acc[oy][3];
        *(float4*)&outp[o * HWN + p0 + tx * 4]      = make_float4(p0v.x, p0v.y, p1v.x, p1v.y);
        *(float4*)&outp[o * HWN + p0 + 64 + tx * 4] = make_float4(p2v.x, p2v.y, p3v.x, p3v.y);
        psum[oy] = p0v.x + p0v.y + p1v.x + p1v.y + p2v.x + p2v.y + p3v.x + p3v.y;
    }
    __syncthreads();
    float* red = smem;  // reuse
#pragma unroll
    for (int oy = 0; oy < 8; oy++) red[(ty * 8 + oy) * 16 + tx] = psum[oy];
    __syncthreads();
    if (tid < 64) {
        float s = 0.f;
#pragma unroll
        for (int t = 0; t < 16; t++) s += red[tid * 16 + t];
        g_bsums[((i * 4 + b) * 128 + row) * 64 + tid] = s;
    }
}

// ---------------- K4: SE MLP (tiny, one block) ----------------
__global__ void se_kernel(const float* __restrict__ w1, const float* __restrict__ b1,
                          const float* __restrict__ w2, const float* __restrict__ b2) {
    __shared__ float gm[4 * 256];
    __shared__ float h1[4 * 64];
    int tid = threadIdx.x;  // 256
    for (int idx = tid; idx < 1024; idx += 256) {
        int b = idx >> 8, ch = idx & 255;
        int i = ch >> 6, o = ch & 63;
        float s = 0.f;
        for (int r = 0; r < 128; r++)
            s += g_bsums[((i * 4 + b) * 128 + r) * 64 + o];
        gm[b * 256 + ch] = s * (1.f / 16384.f);
    }
    __syncthreads();
    {
        int b = tid >> 6, oc = tid & 63;
        float a = b1[oc];
        for (int ch = 0; ch < 256; ch++) a += w1[oc * 256 + ch] * gm[b * 256 + ch];
        h1[b * 64 + oc] = fmaxf(a, 0.f);
    }
    __syncthreads();
    for (int idx = tid; idx < 1024; idx += 256) {
        int b = idx >> 8, ch = idx & 255;
        float a = b2[ch];
        for (int oc = 0; oc < 64; oc++) a += w2[ch * 64 + oc] * h1[b * 64 + oc];
        g_gate[b * 256 + ch] = 1.f + 1.f / (1.f + expf(-a));
    }
}

// ---------------- K5: gated fuse + residual ----------------
__global__ void final_kernel(const float* __restrict__ x, float* __restrict__ out) {
    int idx = blockIdx.x * 256 + threadIdx.x;  // < 1048576 float4s
    int p4 = idx & 4095;
    int o  = (idx >> 12) & 63;
    int b  = idx >> 18;
    float4 a = ((const float4*)x)[idx];
#pragma unroll
    for (int i = 0; i < 4; i++) {
        float g = g_gate[b * 256 + i * 64 + o];
        float4 cv = ((const float4*)g_cat)[((i * 4 + b) * 64 + o) * 4096 + p4];
        a.x += g * cv.x;
        a.y += g * cv.y;
        a.z += g * cv.z;
        a.w += g * cv.w;
    }
    ((float4*)out)[idx] = a;
}

extern "C" void kernel_launch(void* const* d_in, const int* in_sizes, int n_in,
                              void* d_out, int out_size) {
    const float* x  = (const float*)d_in[0];
    const float* dw = (const float*)d_in[1];
    const float* ow = (const float*)d_in[2];
    const float* ob = (const float*)d_in[3];
    const float* w1 = (const float*)d_in[4];
    const float* b1 = (const float*)d_in[5];
    const float* w2 = (const float*)d_in[6];
    const float* b2 = (const float*)d_in[7];
    float* out = (float*)d_out;

    const int branch_smem = (2 * 4096 + 2 * 8448) * 4;  // 100352 B -> 2 blocks/SM
    cudaFuncSetAttribute(branch_kernel, cudaFuncAttributeMaxDynamicSharedMemorySize, branch_smem);

    transpose_kernel<<<dim3(512, 2, 4), dim3(32, 8)>>>(x);
    dwt_kernel<<<576, 256>>>(dw);
    offset_kernel<<<dim3(64, 4, 4), 256>>>(x, ow, ob);
    branch_kernel<<<dim3(128, 4, 4), 128, branch_smem>>>();
    se_kernel<<<1, 256>>>(w1, b1, w2, b2);
    final_kernel<<<4096, 256>>>(x, out);
}

// round 6
// speedup vs baseline: 1.0808x; 1.0808x over previous
#include <cuda_runtime.h>

#define HH 128
#define WW 128
#define HWN 16384
#define BHW (4 * 16384)
#define BN 4
#define CN 64

typedef unsigned long long ull;

__device__ __constant__ int c_RATES[4] = {2, 3, 5, 9};

// Scratch (static device globals: allocation-free, graph-capturable)
__device__ float g_xhwc[BN * HWN * CN];            // [b][p][c]
__device__ float g_off[4 * 18 * BHW];              // [j][k2][b*HW+p]  planar
__device__ float g_dwt[4 * 9 * 64 * 64];           // [i][k][c][o]
__device__ float g_cat[4 * BN * CN * HWN];         // [i][b][o][p]
__device__ float g_bsums[4 * BN * 128 * 64];       // [i][b][row][o]
__device__ float g_gate[BN * 256];                 // 1 + sigmoid(...)

__device__ __forceinline__ ull pack2(float a, float b) {
    ull r;
    asm("mov.b64 %0, {%1, %2};" : "=l"(r) : "f"(a), "f"(b));
    return r;
}
__device__ __forceinline__ void ffma2(ull& d, ull a, ull b) {
    asm("fma.rn.f32x2 %0, %1, %2, %0;" : "+l"(d) : "l"(a), "l"(b));
}

// ---------------- K1: NCHW -> NHWC transpose of x ----------------
__global__ void transpose_kernel(const float* __restrict__ x) {
    __shared__ float tile[32][33];
    int b  = blockIdx.z;
    int p0 = blockIdx.x * 32;
    int c0 = blockIdx.y * 32;
    for (int i = threadIdx.y; i < 32; i += 8)
        tile[i][threadIdx.x] = x[(b * 64 + c0 + i) * HWN + p0 + threadIdx.x];
    __syncthreads();
    for (int i = threadIdx.y; i < 32; i += 8)
        g_xhwc[(b * HWN + p0 + i) * 64 + c0 + threadIdx.x] = tile[threadIdx.x][i];
}

// ---------------- K1b: dw (i,o,c,3,3) -> g_dwt [i][k][c][o] ----------------
__global__ void dwt_kernel(const float* __restrict__ dw) {
    int idx = blockIdx.x * 256 + threadIdx.x;  // < 147456
    int i  = idx / 36864;
    int r  = idx % 36864;
    int k  = r / 4096;
    int r2 = r & 4095;
    int c  = r2 >> 6;
    int o  = r2 & 63;
    g_dwt[idx] = dw[((i * 64 + o) * 64 + c) * 9 + k];
}

// ---------------- K2: offset conv (64 -> 18, dilated 3x3, relu), f32x2 ----------------
// writes PLANAR layout: g_off[(j*18+k2)*BHW + b*HWN + p]
__global__ __launch_bounds__(256) void offset_kernel(const float* __restrict__ x,
                                                     const float* __restrict__ ow,
                                                     const float* __restrict__ ob) {
    __shared__ float ow_sh[9 * 64 * 20];
    int j = blockIdx.z, b = blockIdx.y;
    int rate = c_RATES[j];
    int tid = threadIdx.x;
    for (int idx = tid; idx < 9 * 64 * 20; idx += 256) {
        int k2 = idx % 20;
        int rest = idx / 20;
        int c = rest % 64;
        int t = rest / 64;
        ow_sh[idx] = (k2 < 18) ? ow[((j * 18 + k2) * 64 + c) * 9 + t] : 0.f;
    }
    __syncthreads();

    int p = blockIdx.x * 256 + tid;
    int y = p >> 7, xx = p & 127;
    ull acc2[10];
#pragma unroll
    for (int q = 0; q < 9; q++) acc2[q] = pack2(ob[j * 18 + 2 * q], ob[j * 18 + 2 * q + 1]);
    acc2[9] = 0ull;

    const float* xb = x + b * 64 * HWN;
    for (int t = 0; t < 9; t++) {
        int tyv = y + (t / 3 - 1) * rate;
        int txv = xx + (t % 3 - 1) * rate;
        if ((unsigned)tyv >= HH || (unsigned)txv >= WW) continue;
        const float* xp = xb + tyv * WW + txv;
#pragma unroll 4
        for (int c = 0; c < 64; c++) {
            float xc = xp[c * HWN];  // coalesced across warp
            ull xcc = pack2(xc, xc);
            const ull* wr = (const ull*)&ow_sh[(t * 64 + c) * 20];  // broadcast
#pragma unroll
            for (int q = 0; q < 10; q++) ffma2(acc2[q], wr[q], xcc);
        }
    }
    float* og = g_off + j * 18 * BHW + b * HWN + p;  // plane stride BHW, coalesced
#pragma unroll
    for (int q = 0; q < 9; q++) {
        float2 v = *(float2*)&acc2[q];
        og[(2 * q) * BHW]     = fmaxf(v.x, 0.f);
        og[(2 * q + 1) * BHW] = fmaxf(v.y, 0.f);
    }
}

// ---------------- K3: deform sample + GEMM per branch ----------------
// block = full image row (128 px) x 64 outputs, 128 threads, 8x8 tile, f32x2
// S tile uses pixel-rotation swizzle: phys(sp, c) = (sp + 4*(c>>2)) & 127
// gather: 8 lanes per pixel (full-line LDG.128), conflict-free STS
#define SPITCH 132
__global__ __launch_bounds__(128, 4) void branch_kernel() {
    extern __shared__ float smem[];
    float* A_sh = smem;                  // 64*64   = 4096 floats
    float* S_sh = smem + 4096;           // 64*132  = 8448 floats

    int i = blockIdx.z, b = blockIdx.y, row = blockIdx.x;
    int p0 = row * 128;
    int j = (i + 3) & 3;
    int rate = c_RATES[i];
    int tid = threadIdx.x;
    int tx = tid & 15, ty = tid >> 4;
    int warp = tid >> 5;
    int lane8 = tid & 7;          // 16B channel chunk index
    int pxi   = (tid >> 3) & 3;   // pixel within 4-px group

    ull acc[8][4];
#pragma unroll
    for (int oy = 0; oy < 8; oy++)
#pragma unroll
        for (int q = 0; q < 4; q++) acc[oy][q] = 0ull;

    const float* xb   = &g_xhwc[b * HWN * 64];
    const float* dwt  = &g_dwt[i * 9 * 4096];
    const float* offb = g_off + j * 18 * BHW + b * HWN + p0;

    int ca = lane8 * 4;           // channels [ca, ca+4) and [ca+32, ca+36)
    int sha = 4 * lane8;          // swizzle shift for chunk a
    int shb = 4 * lane8 + 32;     // swizzle shift for chunk b

    for (int k = 0; k < 9; k++) {
        __syncthreads();
        // stage A (dw k-chunk): 4096 floats
        {
            const float4* src = (const float4*)(dwt + k * 4096);
            float4* dst = (float4*)A_sh;
#pragma unroll
            for (int u = 0; u < 8; u++) dst[tid + u * 128] = src[tid + u * 128];
        }
        // gather: 8 groups of 4 pixels per warp; each thread: 1 pixel, 8 channels
        int kyr = (k / 3 - 1) * rate;
        int kxr = (k % 3 - 1) * rate;
        const float* offY = offb + (2 * k) * BHW;
        const float* offX = offb + (2 * k + 1) * BHW;
#pragma unroll 2
        for (int g = 0; g < 8; g++) {
            int sp = warp * 32 + g * 4 + pxi;
            float dy = __ldg(offY + sp);
            float dx = __ldg(offX + sp);
            float py = (float)(row + kyr) + dy;
            float px = (float)(sp + kxr) + dx;
            float fy = floorf(py), fx = floorf(px);
            int iy0 = (int)fy, ix0 = (int)fx;
            float wy1 = py - fy, wx1 = px - fx;
            float wy0 = 1.f - wy1, wx0 = 1.f - wx1;
            bool vy0 = (unsigned)iy0 < HH, vy1 = (unsigned)(iy0 + 1) < HH;
            bool vx0 = (unsigned)ix0 < WW, vx1 = (unsigned)(ix0 + 1) < WW;
            float w00 = (vy0 && vx0) ? wy0 * wx0 : 0.f;
            float w01 = (vy0 && vx1) ? wy0 * wx1 : 0.f;
            float w10 = (vy1 && vx0) ? wy1 * wx0 : 0.f;
            float w11 = (vy1 && vx1) ? wy1 * wx1 : 0.f;
            ull w00d = pack2(w00, w00), w01d = pack2(w01, w01);
            ull w10d = pack2(w10, w10), w11d = pack2(w11, w11);
            int cy0 = min(max(iy0, 0), HH - 1), cy1 = min(max(iy0 + 1, 0), HH - 1);
            int cx0 = min(max(ix0, 0), WW - 1), cx1 = min(max(ix0 + 1, 0), WW - 1);
            const float* b00 = xb + (cy0 * WW + cx0) * 64;
            const float* b01 = xb + (cy0 * WW + cx1) * 64;
            const float* b10 = xb + (cy1 * WW + cx0) * 64;
            const float* b11 = xb + (cy1 * WW + cx1) * 64;
            // chunk a: channels [ca, ca+4)  (full 128B lines across the 4-px group)
            {
                ulonglong2 t00 = *(const ulonglong2*)(b00 + ca);
                ulonglong2 t01 = *(const ulonglong2*)(b01 + ca);
                ulonglong2 t10 = *(const ulonglong2*)(b10 + ca);
                ulonglong2 t11 = *(const ulonglong2*)(b11 + ca);
                ull r0 = 0, r1 = 0;
                ffma2(r0, w00d, t00.x); ffma2(r1, w00d, t00.y);
                ffma2(r0, w01d, t01.x); ffma2(r1, w01d, t01.y);
                ffma2(r0, w10d, t10.x); ffma2(r1, w10d, t10.y);
                ffma2(r0, w11d, t11.x); ffma2(r1, w11d, t11.y);
                float2 f0 = *(float2*)&r0, f1 = *(float2*)&r1;
                int pa = (sp + sha) & 127;
                float* d = &S_sh[ca * SPITCH + pa];
                d[0]          = f0.x;
                d[SPITCH]     = f0.y;
                d[2 * SPITCH] = f1.x;
                d[3 * SPITCH] = f1.y;
            }
            // chunk b: channels [ca+32, ca+36)
            {
                ulonglong2 t00 = *(const ulonglong2*)(b00 + ca + 32);
                ulonglong2 t01 = *(const ulonglong2*)(b01 + ca + 32);
                ulonglong2 t10 = *(const ulonglong2*)(b10 + ca + 32);
                ulonglong2 t11 = *(const ulonglong2*)(b11 + ca + 32);
                ull r0 = 0, r1 = 0;
                ffma2(r0, w00d, t00.x); ffma2(r1, w00d, t00.y);
                ffma2(r0, w01d, t01.x); ffma2(r1, w01d, t01.y);
                ffma2(r0, w10d, t10.x); ffma2(r1, w10d, t10.y);
                ffma2(r0, w11d, t11.x); ffma2(r1, w11d, t11.y);
                float2 f0 = *(float2*)&r0, f1 = *(float2*)&r1;
                int pb = (sp + shb) & 127;
                float* d = &S_sh[(ca + 32) * SPITCH + pb];
                d[0]          = f0.x;
                d[SPITCH]     = f0.y;
                d[2 * SPITCH] = f1.x;
                d[3 * SPITCH] = f1.y;
            }
        }
        __syncthreads();
        // GEMM: acc[oy][pp] += dup(A[c][ty*8+oy]) * S pixel-pairs (swizzled load)
#pragma unroll 4
        for (int c = 0; c < 64; c++) {
            float4 a0 = *(const float4*)&A_sh[c * 64 + ty * 8];
            float4 a1 = *(const float4*)&A_sh[c * 64 + ty * 8 + 4];
            int sh = c & ~3;  // 4*(c>>2)
            ulonglong2 B0 = *(const ulonglong2*)&S_sh[c * SPITCH + ((tx * 4 + sh) & 127)];
            ulonglong2 B1 = *(const ulonglong2*)&S_sh[c * SPITCH + ((tx * 4 + 64 + sh) & 127)];
            ull aa;
            aa = pack2(a0.x, a0.x); ffma2(acc[0][0], aa, B0.x); ffma2(acc[0][1], aa, B0.y); ffma2(acc[0][2], aa, B1.x); ffma2(acc[0][3], aa, B1.y);
            aa = pack2(a0.y, a0.y); ffma2(acc[1][0], aa, B0.x); ffma2(acc[1][1], aa, B0.y); ffma2(acc[1][2], aa, B1.x); ffma2(acc[1][3], aa, B1.y);
            aa = pack2(a0.z, a0.z); ffma2(acc[2][0], aa, B0.x); ffma2(acc[2][1], aa, B0.y); ffma2(acc[2][2], aa, B1.x); ffma2(acc[2][3], aa, B1.y);
            aa = pack2(a0.w, a0.w); ffma2(acc[3][0], aa, B0.x); ffma2(acc[3][1], aa, B0.y); ffma2(acc[3][2], aa, B1.x); ffma2(acc[3][3], aa, B1.y);
            aa = pack2(a1.x, a1.x); ffma2(acc[4][0], aa, B0.x); ffma2(acc[4][1], aa, B0.y); ffma2(acc[4][2], aa, B1.x); ffma2(acc[4][3], aa, B1.y);
            aa = pack2(a1.y, a1.y); ffma2(acc[5][0], aa, B0.x); ffma2(acc[5][1], aa, B0.y); ffma2(acc[5][2], aa, B1.x); ffma2(acc[5][3], aa, B1.y);
            aa = pack2(a1.z, a1.z); ffma2(acc[6][0], aa, B0.x); ffma2(acc[6][1], aa, B0.y); ffma2(acc[6][2], aa, B1.x); ffma2(acc[6][3], aa, B1.y);
            aa = pack2(a1.w, a1.w); ffma2(acc[7][0], aa, B0.x); ffma2(acc[7][1], aa, B0.y); ffma2(acc[7][2], aa, B1.x); ffma2(acc[7][3], aa, B1.y);
        }
    }

    // write outputs + per-row channel sums (deterministic)
    float* outp = &g_cat[((i * 4 + b) * 64) * HWN];
    float psum[8];
#pragma unroll
    for (int oy = 0; oy < 8; oy++) {
        int o = ty * 8 + oy;
        float2 p0v = *(float2*)&acc[oy][0];
        float2 p1v = *(float2*)&acc[oy][1];
        float2 p2v = *(float2*)&acc[oy][2];
        float2 p3v = *(float2*)&acc[oy][3];
        *(float4*)&outp[o * HWN + p0 + tx * 4]      = make_float4(p0v.x, p0v.y, p1v.x, p1v.y);
        *(float4*)&outp[o * HWN + p0 + 64 + tx * 4] = make_float4(p2v.x, p2v.y, p3v.x, p3v.y);
        psum[oy] = p0v.x + p0v.y + p1v.x + p1v.y + p2v.x + p2v.y + p3v.x + p3v.y;
    }
    __syncthreads();
    float* red = A_sh;  // reuse (GEMM done)
#pragma unroll
    for (int oy = 0; oy < 8; oy++) red[(ty * 8 + oy) * 16 + tx] = psum[oy];
    __syncthreads();
    if (tid < 64) {
        float s = 0.f;
#pragma unroll
        for (int t = 0; t < 16; t++) s += red[tid * 16 + t];
        g_bsums[((i * 4 + b) * 128 + row) * 64 + tid] = s;
    }
}

// ---------------- K4: SE MLP (tiny, one block) ----------------
__global__ void se_kernel(const float* __restrict__ w1, const float* __restrict__ b1,
                          const float* __restrict__ w2, const float* __restrict__ b2) {
    __shared__ float gm[4 * 256];
    __shared__ float h1[4 * 64];
    int tid = threadIdx.x;  // 256
    for (int idx = tid; idx < 1024; idx += 256) {
        int b = idx >> 8, ch = idx & 255;
        int i = ch >> 6, o = ch & 63;
        float s = 0.f;
        for (int r = 0; r < 128; r++)
            s += g_bsums[((i * 4 + b) * 128 + r) * 64 + o];
        gm[b * 256 + ch] = s * (1.f / 16384.f);
    }
    __syncthreads();
    {
        int b = tid >> 6, oc = tid & 63;
        float a = b1[oc];
        for (int ch = 0; ch < 256; ch++) a += w1[oc * 256 + ch] * gm[b * 256 + ch];
        h1[b * 64 + oc] = fmaxf(a, 0.f);
    }
    __syncthreads();
    for (int idx = tid; idx < 1024; idx += 256) {
        int b = idx >> 8, ch = idx & 255;
        float a = b2[ch];
        for (int oc = 0; oc < 64; oc++) a += w2[ch * 64 + oc] * h1[b * 64 + oc];
        g_gate[b * 256 + ch] = 1.f + 1.f / (1.f + expf(-a));
    }
}

// ---------------- K5: gated fuse + residual ----------------
__global__ void final_kernel(const float* __restrict__ x, float* __restrict__ out) {
    int idx = blockIdx.x * 256 + threadIdx.x;  // < 1048576 float4s
    int p4 = idx & 4095;
    int o  = (idx >> 12) & 63;
    int b  = idx >> 18;
    float4 a = ((const float4*)x)[idx];
#pragma unroll
    for (int i = 0; i < 4; i++) {
        float g = g_gate[b * 256 + i * 64 + o];
        float4 cv = ((const float4*)g_cat)[((i * 4 + b) * 64 + o) * 4096 + p4];
        a.x += g * cv.x;
        a.y += g * cv.y;
        a.z += g * cv.z;
        a.w += g * cv.w;
    }
    ((float4*)out)[idx] = a;
}

extern "C" void kernel_launch(void* const* d_in, const int* in_sizes, int n_in,
                              void* d_out, int out_size) {
    const float* x  = (const float*)d_in[0];
    const float* dw = (const float*)d_in[1];
    const float* ow = (const float*)d_in[2];
    const float* ob = (const float*)d_in[3];
    const float* w1 = (const float*)d_in[4];
    const float* b1 = (const float*)d_in[5];
    const float* w2 = (const float*)d_in[6];
    const float* b2 = (const float*)d_in[7];
    float* out = (float*)d_out;

    const int branch_smem = (4096 + 8448) * 4;  // 50176 B -> 4 blocks/SM
    cudaFuncSetAttribute(branch_kernel, cudaFuncAttributeMaxDynamicSharedMemorySize, branch_smem);

    transpose_kernel<<<dim3(512, 2, 4), dim3(32, 8)>>>(x);
    dwt_kernel<<<576, 256>>>(dw);
    offset_kernel<<<dim3(64, 4, 4), 256>>>(x, ow, ob);
    branch_kernel<<<dim3(128, 4, 4), 128, branch_smem>>>();
    se_kernel<<<1, 256>>>(w1, b1, w2, b2);
    final_kernel<<<4096, 256>>>(x, out);
}